// round 15
// baseline (speedup 1.0000x reference)
#include <cuda_runtime.h>
#include <cuda_fp16.h>
#include <cstdint>

// ---------------------------------------------------------------------------
// SGCEncoder: out = prop(relu(prop(x) @ W1 + b1)) @ W2 + b2
//   prop = D^-1/2 (A+I) D^-1/2
// Rewrites:
//   prop(x)[d] = dinv[d] * ( sum_{s->d} xs[s] + xs[d] ),  xs = x*dinv (fp16)
//   prop(H1) @ W2 = prop(H1 @ W2)          (propagate at D=128, fp16 source)
// Round 15: R11 structure + single-kernel scan (last-block computes boff;
//           scan3 eliminated; boff added inline in fill/gathers).
// ---------------------------------------------------------------------------

#define N_NODES 50000
#define M_PAD   50048          // 391 * 128
#define D0      256
#define D2      128
#define E_MAX   1600000
#define NTILE_M 391
#define TILE0   196            // chunk0 tiles
#define TILE1   (NTILE_M - TILE0)
#define ROWHALF (TILE0 * 128)  // 25088

__device__ int    g_deg   [M_PAD];     // zero at entry; restored by k_scan1
__device__ int    g_rowptr[M_PAD + 1]; // block-LOCAL exclusive prefixes
__device__ int    g_rank  [E_MAX];     // edge rank within its destination
__device__ int    g_esrc  [E_MAX];
__device__ int    g_bsum  [64];
__device__ int    g_boff  [64];
__device__ int    g_ticket;            // zero at entry; reset by last block
__device__ float  g_dinv  [M_PAD];
__device__ __half g_xh    [M_PAD * D0];  // xs = x * dinv, fp16 (hop-1 src)
__device__ __half g_gsh   [M_PAD * D2];  // (H1 @ W2) * dinv, fp16 (hop-2 src)
__device__ __half g_ah    [M_PAD * D0];  // hop-1 result (GEMM1 A), fp16
__device__ __half g_h1h   [M_PAD * D0];  // relu(..) (GEMM2 A), fp16
__device__ __half g_w1    [D0 * D0];     // W1^T [n][k] fp16
__device__ __half g_w2    [D2 * D0];     // W2^T [n][k] fp16

__global__ void k_noop() {}

// --------------------------- setup: deg histogram (+rank) + weight cvt ------

__global__ void k_deg_wsplit(const int* __restrict__ dst, int E,
                             const float* __restrict__ W1,
                             const float* __restrict__ W2, int nDegBlocks) {
    if ((int)blockIdx.x < nDegBlocks) {
        int base = blockIdx.x * 1024 + threadIdx.x;
#pragma unroll
        for (int u = 0; u < 4; u++) {
            int i = base + u * 256;
            if (i < E) {
                int d = __ldg(&dst[i]);
                g_rank[i] = atomicAdd(&g_deg[d], 1);
            }
        }
    } else {
        int i = (blockIdx.x - nDegBlocks) * 256 + threadIdx.x;
        if (i < D0 * D0) {
            int n = i >> 8, k = i & 255;
            g_w1[n * D0 + k] = __float2half_rn(W1[k * D0 + n]);
        } else if (i < D0 * D0 + D2 * D0) {
            int j = i - D0 * D0;
            int n = j >> 8, k = j & 255;
            g_w2[n * D0 + k] = __float2half_rn(W2[k * D2 + n]);
        }
    }
}

// fused: read deg, zero deg, dinv, block-LOCAL scan, last block computes boff
__global__ void __launch_bounds__(1024) k_scan1() {
    __shared__ int warp_red[32];
    __shared__ int amLast;
    const int tid = threadIdx.x, lane = tid & 31, wid = tid >> 5;
    int idx = blockIdx.x * 1024 + tid;
    int v = 0;
    if (idx < M_PAD) {
        v = g_deg[idx];
        g_deg[idx] = 0;
        g_dinv[idx] = (idx < N_NODES) ? rsqrtf((float)(v + 1)) : 0.0f;
    }
    int inc = v;
#pragma unroll
    for (int off = 1; off < 32; off <<= 1) {
        int t = __shfl_up_sync(0xffffffff, inc, off);
        if (lane >= off) inc += t;
    }
    if (lane == 31) warp_red[wid] = inc;
    __syncthreads();
    if (wid == 0) {
        int w = warp_red[lane];
#pragma unroll
        for (int off = 1; off < 32; off <<= 1) {
            int t = __shfl_up_sync(0xffffffff, w, off);
            if (lane >= off) w += t;
        }
        warp_red[lane] = w;
    }
    __syncthreads();
    int excl = ((wid > 0) ? warp_red[wid - 1] : 0) + (inc - v);
    if (idx <= M_PAD) g_rowptr[idx] = excl;     // block-local prefixes

    // publish block sum, then the last-arriving block builds g_boff
    if (tid == 0) {
        g_bsum[blockIdx.x] = warp_red[31];
        __threadfence();
        int t = atomicAdd(&g_ticket, 1);
        amLast = (t == (int)gridDim.x - 1);
    }
    __syncthreads();
    if (amLast) {
        __threadfence();                        // acquire: see all g_bsum
        if (tid < 64) {
            __shared__ int wsum2[2];
            int l = tid & 31, w2 = tid >> 5;
            int bv = ((int)tid < (int)gridDim.x) ? g_bsum[tid] : 0;
            int binc = bv;
#pragma unroll
            for (int off = 1; off < 32; off <<= 1) {
                int s = __shfl_up_sync(0xffffffff, binc, off);
                if (l >= off) binc += s;
            }
            if (l == 31) wsum2[w2] = binc;
            __syncwarp();
            if (tid == 31) { /* ensure wsum2[0] written before warp1 reads */ }
            __syncthreads();
            int bexcl = binc - bv + ((w2 == 1) ? wsum2[0] : 0);
            g_boff[tid] = bexcl;
        } else {
            __syncthreads();
        }
        if (tid == 0) g_ticket = 0;             // reset for next graph replay
    }
}

// atomic-free fill: pos = rowptr[dst] + boff[dst>>10] + rank
__global__ void k_fill(const int* __restrict__ src, const int* __restrict__ dst, int E) {
    int base = blockIdx.x * 1024 + threadIdx.x;
#pragma unroll
    for (int u = 0; u < 4; u++) {
        int i = base + u * 256;
        if (i < E) {
            int d = __ldg(&dst[i]);
            int r = __ldg(&g_rank[i]);
            int pos = __ldg(&g_rowptr[d]) + __ldg(&g_boff[d >> 10]) + r;
            g_esrc[pos] = __ldg(&src[i]);
        }
    }
}

// --------------------------- xs = x*dinv (fp16) ------------------------------

__global__ void k_scale_h(const float* __restrict__ x) {
    int i = blockIdx.x * blockDim.x + threadIdx.x;      // float4 index
    if (i >= M_PAD * (D0 / 4)) return;
    int row = i >> 6;
    float4 v = make_float4(0.f, 0.f, 0.f, 0.f);
    if (row < N_NODES) {
        v = ((const float4*)x)[i];
        float s = g_dinv[row];
        v.x *= s; v.y *= s; v.z *= s; v.w *= s;
    }
    __half2 h0 = __floats2half2_rn(v.x, v.y);
    __half2 h1 = __floats2half2_rn(v.z, v.w);
    uint2 o;
    o.x = *reinterpret_cast<uint32_t*>(&h0);
    o.y = *reinterpret_cast<uint32_t*>(&h1);
    ((uint2*)g_xh)[i] = o;
}

// --------------------------- helpers -----------------------------------------

__device__ __forceinline__ uint32_t packh2(float a, float b) {
    __half2 h = __floats2half2_rn(a, b);
    return *reinterpret_cast<uint32_t*>(&h);
}
__device__ __forceinline__ void acc8(float* a, uint4 v) {
    const __half2* h = reinterpret_cast<const __half2*>(&v);
    float2 f0 = __half22float2(h[0]);
    float2 f1 = __half22float2(h[1]);
    float2 f2 = __half22float2(h[2]);
    float2 f3 = __half22float2(h[3]);
    a[0] += f0.x; a[1] += f0.y; a[2] += f1.x; a[3] += f1.y;
    a[4] += f2.x; a[5] += f2.y; a[6] += f3.x; a[7] += f3.y;
}
__device__ __forceinline__ void acc4(float* a, uint2 v) {
    const __half2* h = reinterpret_cast<const __half2*>(&v);
    float2 f0 = __half22float2(h[0]);
    float2 f1 = __half22float2(h[1]);
    a[0] += f0.x; a[1] += f0.y; a[2] += f1.x; a[3] += f1.y;
}
__device__ __forceinline__ int row_beg(int w) {
    return __ldg(&g_rowptr[w]) + __ldg(&g_boff[w >> 10]);
}

// --------------------------- gathers ----------------------------------------

// hop-1 gather over rows [rowBeg, rowEnd): warp per dst row; lane owns 8 elems.
__global__ void __launch_bounds__(256) k_gather256(int rowBeg, int rowEnd) {
    int w = rowBeg + ((blockIdx.x * blockDim.x + threadIdx.x) >> 5);
    if (w >= rowEnd) return;
    const int lane = threadIdx.x & 31;
    float a[8];
#pragma unroll
    for (int j = 0; j < 8; j++) a[j] = 0.f;
    if (w < N_NODES) {
        const uint4* xh = (const uint4*)g_xh;   // row stride 32 uint4
        acc8(a, __ldg(&xh[(size_t)w * 32 + lane]));   // self term
        int e   = row_beg(w);
        int end = row_beg(w + 1);
        for (; e + 3 < end; e += 4) {
            int s0 = __ldg(&g_esrc[e]);
            int s1 = __ldg(&g_esrc[e + 1]);
            int s2 = __ldg(&g_esrc[e + 2]);
            int s3 = __ldg(&g_esrc[e + 3]);
            uint4 v0 = __ldg(&xh[(size_t)s0 * 32 + lane]);
            uint4 v1 = __ldg(&xh[(size_t)s1 * 32 + lane]);
            uint4 v2 = __ldg(&xh[(size_t)s2 * 32 + lane]);
            uint4 v3 = __ldg(&xh[(size_t)s3 * 32 + lane]);
            acc8(a, v0); acc8(a, v1); acc8(a, v2); acc8(a, v3);
        }
        for (; e < end; e++) {
            int s0 = __ldg(&g_esrc[e]);
            acc8(a, __ldg(&xh[(size_t)s0 * 32 + lane]));
        }
        float sd = g_dinv[w];
#pragma unroll
        for (int j = 0; j < 8; j++) a[j] *= sd;
    }
    uint4 o;
    o.x = packh2(a[0], a[1]);
    o.y = packh2(a[2], a[3]);
    o.z = packh2(a[4], a[5]);
    o.w = packh2(a[6], a[7]);
    ((uint4*)g_ah)[(size_t)w * 32 + lane] = o;
}

// hop-2 gather, D=128 fp16 src: warp per dst row; lane owns 4 elements.
__global__ void __launch_bounds__(256) k_gather128(const float* __restrict__ b2,
                                                   float* __restrict__ out) {
    int w = (blockIdx.x * blockDim.x + threadIdx.x) >> 5;
    if (w >= N_NODES) return;
    const int lane = threadIdx.x & 31;
    const uint2* gs = (const uint2*)g_gsh;      // row stride 32 uint2
    float a[4] = {0.f, 0.f, 0.f, 0.f};
    acc4(a, __ldg(&gs[(size_t)w * 32 + lane]));
    int e   = row_beg(w);
    int end = row_beg(w + 1);
    for (; e + 3 < end; e += 4) {
        int s0 = __ldg(&g_esrc[e]);
        int s1 = __ldg(&g_esrc[e + 1]);
        int s2 = __ldg(&g_esrc[e + 2]);
        int s3 = __ldg(&g_esrc[e + 3]);
        uint2 v0 = __ldg(&gs[(size_t)s0 * 32 + lane]);
        uint2 v1 = __ldg(&gs[(size_t)s1 * 32 + lane]);
        uint2 v2 = __ldg(&gs[(size_t)s2 * 32 + lane]);
        uint2 v3 = __ldg(&gs[(size_t)s3 * 32 + lane]);
        acc4(a, v0); acc4(a, v1); acc4(a, v2); acc4(a, v3);
    }
    for (; e < end; e++) {
        int s0 = __ldg(&g_esrc[e]);
        acc4(a, __ldg(&gs[(size_t)s0 * 32 + lane]));
    }
    float s = g_dinv[w];
    float4 b = __ldg(&((const float4*)b2)[lane]);
    float4 o;
    o.x = a[0] * s + b.x;
    o.y = a[1] * s + b.y;
    o.z = a[2] * s + b.z;
    o.w = a[3] * s + b.w;
    ((float4*)out)[(size_t)w * 32 + lane] = o;
}

// --------------------------- HMMA GEMM (cp.async pipelined) -----------------

__device__ __forceinline__ uint32_t smem_u32(const void* p) {
    return (uint32_t)__cvta_generic_to_shared(p);
}
__device__ __forceinline__ void cp16(uint32_t s, const void* g) {
    asm volatile("cp.async.cg.shared.global [%0], [%1], 16;" :: "r"(s), "l"(g));
}
#define CP_COMMIT() asm volatile("cp.async.commit_group;" ::: "memory")
#define CP_WAIT(n)  asm volatile("cp.async.wait_group %0;" :: "n"(n) : "memory")

__device__ __forceinline__ void ldsm_x4(uint32_t& r0, uint32_t& r1,
                                        uint32_t& r2, uint32_t& r3, uint32_t a) {
    asm volatile("ldmatrix.sync.aligned.m8n8.x4.shared.b16 {%0,%1,%2,%3}, [%4];"
                 : "=r"(r0), "=r"(r1), "=r"(r2), "=r"(r3) : "r"(a));
}
__device__ __forceinline__ void mma16816(float* d, const uint32_t* a, const uint32_t* b) {
    asm volatile(
        "mma.sync.aligned.m16n8k16.row.col.f32.f16.f16.f32 "
        "{%0,%1,%2,%3}, {%4,%5,%6,%7}, {%8,%9}, {%0,%1,%2,%3};"
        : "+f"(d[0]), "+f"(d[1]), "+f"(d[2]), "+f"(d[3])
        : "r"(a[0]), "r"(a[1]), "r"(a[2]), "r"(a[3]), "r"(b[0]), "r"(b[1]));
}

#define BK      32
#define LDS     40                     // padded row stride (elements)
#define BUFB    (128 * LDS * 2)        // 10240 bytes per tile buffer
#define SM_MMA  (4 * BUFB)             // 40960 bytes (2 stages x 2 buffers)

template<int MODE>
__global__ void __launch_bounds__(256)
k_mma(const float* __restrict__ bias, int tileOff) {
    extern __shared__ char dynsmem[];
    const uint32_t sb = smem_u32(dynsmem);

    const int tid  = threadIdx.x;
    const int lane = tid & 31;
    const int wy   = (tid >> 5) & 1;
    const int wx   = (tid >> 5) >> 1;
    const size_t rowBase = (size_t)(tileOff + blockIdx.y) * 128;
    const int    colBase = blockIdx.x * 128;

    const __half* A = (MODE == 1) ? g_ah : g_h1h;
    const __half* B = (MODE == 1) ? g_w1 : g_w2;

    float acc[4][4][4];
#pragma unroll
    for (int i = 0; i < 4; i++)
#pragma unroll
        for (int j = 0; j < 4; j++)
#pragma unroll
            for (int k = 0; k < 4; k++) acc[i][j][k] = 0.f;

    const int fr = tid >> 1;
    const int fh = (tid & 1) * 16;
    const size_t gA = (rowBase + fr) * 256 + fh;
    const size_t gB = ((size_t)colBase + fr) * 256 + fh;
    const uint32_t dOff = (uint32_t)((fr * LDS + fh) * 2);

    const uint32_t aoff = (uint32_t)(((wy * 64 + (lane & 15)) * LDS + (lane >> 4) * 8) * 2);
    const uint32_t boff = (uint32_t)(((wx * 32 + (lane & 7) + ((lane >> 4) << 3)) * LDS
                                      + (((lane >> 3) & 1) * 8)) * 2);

    auto issue = [&](int kc, int st) {
        const int k0 = kc * BK;
        uint32_t b = sb + (uint32_t)st * (2 * BUFB);
        cp16(b + dOff,      A + gA + k0);
        cp16(b + dOff + 16, A + gA + k0 + 8);
        b += BUFB;
        cp16(b + dOff,      B + gB + k0);
        cp16(b + dOff + 16, B + gB + k0 + 8);
    };

    issue(0, 0);
    CP_COMMIT();

#pragma unroll 1
    for (int kc = 0; kc < 8; kc++) {
        const int cur = kc & 1;
        if (kc < 7) {
            issue(kc + 1, cur ^ 1);
            CP_COMMIT();
            CP_WAIT(1);
        } else {
            CP_WAIT(0);
        }
        __syncthreads();

        const uint32_t sA_b = sb + (uint32_t)cur * (2 * BUFB);
        const uint32_t sB_b = sA_b + BUFB;

#pragma unroll
        for (int ks = 0; ks < 2; ks++) {
            const uint32_t kb = ks * 32;
            uint32_t a[4][4], bh[2][4];
#pragma unroll
            for (int mi = 0; mi < 4; mi++) {
                uint32_t off = aoff + mi * (16 * LDS * 2) + kb;
                ldsm_x4(a[mi][0], a[mi][1], a[mi][2], a[mi][3], sA_b + off);
            }
#pragma unroll
            for (int p = 0; p < 2; p++) {
                uint32_t off = boff + p * (16 * LDS * 2) + kb;
                ldsm_x4(bh[p][0], bh[p][1], bh[p][2], bh[p][3], sB_b + off);
            }
#pragma unroll
            for (int mi = 0; mi < 4; mi++)
#pragma unroll
                for (int ni = 0; ni < 4; ni++) {
                    const int p = ni >> 1, q = (ni & 1) * 2;
                    uint32_t b0[2] = { bh[p][q], bh[p][q + 1] };
                    mma16816(acc[mi][ni], a[mi], b0);
                }
        }
        __syncthreads();
    }

    const int gid = lane >> 2, tig = lane & 3;
#pragma unroll
    for (int mi = 0; mi < 4; mi++) {
        const int row = (int)rowBase + wy * 64 + mi * 16 + gid;
#pragma unroll
        for (int ni = 0; ni < 4; ni++) {
            const int col = colBase + wx * 32 + ni * 8 + tig * 2;
            float d0 = acc[mi][ni][0], d1 = acc[mi][ni][1];
            float d2 = acc[mi][ni][2], d3 = acc[mi][ni][3];
            if (MODE == 1) {
                float b0 = __ldg(&bias[col]), b1 = __ldg(&bias[col + 1]);
                float v0 = fmaxf(d0 + b0, 0.f), v1 = fmaxf(d1 + b1, 0.f);
                float v2 = fmaxf(d2 + b0, 0.f), v3 = fmaxf(d3 + b1, 0.f);
                *(uint32_t*)(g_h1h + (size_t)row * 256 + col)       = packh2(v0, v1);
                *(uint32_t*)(g_h1h + (size_t)(row + 8) * 256 + col) = packh2(v2, v3);
            } else {
                float s0 = g_dinv[row], s1 = g_dinv[row + 8];
                *(uint32_t*)(g_gsh + (size_t)row * 128 + col)       = packh2(d0 * s0, d1 * s0);
                *(uint32_t*)(g_gsh + (size_t)(row + 8) * 128 + col) = packh2(d2 * s1, d3 * s1);
            }
        }
    }
}

// ---------------------------------------------------------------------------

struct HxCtx {
    cudaStream_t s2 = nullptr;
    cudaEvent_t evScale = nullptr, evG0 = nullptr, evM0 = nullptr, evFork = nullptr;
    bool ok = false;
    void init() {
        if (cudaStreamCreateWithFlags(&s2, cudaStreamNonBlocking) != cudaSuccess) return;
        cudaEventCreateWithFlags(&evScale, cudaEventDisableTiming);
        cudaEventCreateWithFlags(&evG0, cudaEventDisableTiming);
        cudaEventCreateWithFlags(&evM0, cudaEventDisableTiming);
        cudaEventCreateWithFlags(&evFork, cudaEventDisableTiming);
        cudaFuncSetAttribute(k_mma<1>, cudaFuncAttributeMaxDynamicSharedMemorySize, SM_MMA);
        cudaFuncSetAttribute(k_mma<2>, cudaFuncAttributeMaxDynamicSharedMemorySize, SM_MMA);
        k_noop<<<1, 32>>>();
        k_noop<<<1, 32, 0, s2>>>();
        cudaStreamSynchronize(s2);
        cudaStreamSynchronize(0);
        ok = true;
    }
};

extern "C" void kernel_launch(void* const* d_in, const int* in_sizes, int n_in,
                              void* d_out, int out_size) {
    const float* x  = (const float*)d_in[0];
    const int*   ei = (const int*)  d_in[1];
    const float* W1 = (const float*)d_in[2];
    const float* b1 = (const float*)d_in[3];
    const float* W2 = (const float*)d_in[4];
    const float* b2 = (const float*)d_in[5];
    float* out = (float*)d_out;

    const int E = in_sizes[1] / 2;
    const int* src = ei;
    const int* dst = ei + E;
    const int nb = (M_PAD + 1023) / 1024;              // 49
    const int nDegBlocks = (E + 1023) / 1024;
    const int nSplitBlocks = (D0 * D0 + D2 * D0 + 255) / 256;

    static HxCtx ctx;
    cudaStreamCaptureStatus cap = cudaStreamCaptureStatusNone;
    cudaStreamIsCapturing(0, &cap);
    if (!ctx.ok && cap == cudaStreamCaptureStatusNone) ctx.init();
    if (!ctx.ok) {
        cudaFuncSetAttribute(k_mma<1>, cudaFuncAttributeMaxDynamicSharedMemorySize, SM_MMA);
        cudaFuncSetAttribute(k_mma<2>, cudaFuncAttributeMaxDynamicSharedMemorySize, SM_MMA);
    }

    if (ctx.ok) {
        cudaStream_t s2 = ctx.s2;

        k_deg_wsplit<<<nDegBlocks + nSplitBlocks, 256>>>(dst, E, W1, W2, nDegBlocks);
        k_scan1<<<nb, 1024>>>();
        cudaEventRecord(ctx.evFork, 0);

        // s2: scale_h (needs dinv only) overlaps fill
        cudaStreamWaitEvent(s2, ctx.evFork, 0);
        k_scale_h<<<(M_PAD * (D0 / 4) + 255) / 256, 256, 0, s2>>>(x);
        cudaEventRecord(ctx.evScale, s2);

        k_fill<<<(E + 1023) / 1024, 256>>>(src, dst, E);
        cudaStreamWaitEvent(0, ctx.evScale, 0);

        // chunk 0 gather, then fork its GEMMs to s2 while chunk 1 gathers
        k_gather256<<<(ROWHALF * 32 + 255) / 256, 256>>>(0, ROWHALF);
        cudaEventRecord(ctx.evG0, 0);

        cudaStreamWaitEvent(s2, ctx.evG0, 0);
        k_mma<1><<<dim3(2, TILE0), 256, SM_MMA, s2>>>(b1, 0);
        k_mma<2><<<dim3(1, TILE0), 256, SM_MMA, s2>>>(nullptr, 0);
        cudaEventRecord(ctx.evM0, s2);

        k_gather256<<<((M_PAD - ROWHALF) * 32 + 255) / 256, 256>>>(ROWHALF, M_PAD);
        k_mma<1><<<dim3(2, TILE1), 256, SM_MMA>>>(b1, TILE0);
        k_mma<2><<<dim3(1, TILE1), 256, SM_MMA>>>(nullptr, TILE0);

        cudaStreamWaitEvent(0, ctx.evM0, 0);
        k_gather128<<<(N_NODES * 32 + 255) / 256, 256>>>(b2, out);
    } else {
        // serial fallback
        k_deg_wsplit<<<nDegBlocks + nSplitBlocks, 256>>>(dst, E, W1, W2, nDegBlocks);
        k_scan1<<<nb, 1024>>>();
        k_fill<<<(E + 1023) / 1024, 256>>>(src, dst, E);
        k_scale_h<<<(M_PAD * (D0 / 4) + 255) / 256, 256>>>(x);
        k_gather256<<<(M_PAD * 32 + 255) / 256, 256>>>(0, M_PAD);
        k_mma<1><<<dim3(2, NTILE_M), 256, SM_MMA>>>(b1, 0);
        k_mma<2><<<dim3(1, NTILE_M), 256, SM_MMA>>>(nullptr, 0);
        k_gather128<<<(N_NODES * 32 + 255) / 256, 256>>>(b2, out);
    }
}

// round 16
// speedup vs baseline: 1.0105x; 1.0105x over previous
#include <cuda_runtime.h>
#include <cuda_fp16.h>
#include <cstdint>

// ---------------------------------------------------------------------------
// SGCEncoder: out = prop(relu(prop(x) @ W1 + b1)) @ W2 + b2
//   prop = D^-1/2 (A+I) D^-1/2
// Rewrites:
//   prop(x)[d] = dinv[d] * ( sum_{s->d} xs[s] + xs[d] ),  xs = x*dinv (fp16)
//   prop(H1) @ W2 = prop(H1 @ W2)          (propagate at D=128, fp16 source)
// Round 16: exact Round-11 configuration (measured best: 197.1us).
//   - CSR-by-dst via rank trick (atomic-free fill)
//   - fp16 gather sources both hops, fp32 accumulation
//   - fp16 single-product cp.async-pipelined HMMA GEMMs
//   - stream-forked scale_h + chunk-0 GEMM overlap
// ---------------------------------------------------------------------------

#define N_NODES 50000
#define M_PAD   50048          // 391 * 128
#define D0      256
#define D2      128
#define E_MAX   1600000
#define NTILE_M 391
#define TILE0   196            // chunk0 tiles
#define TILE1   (NTILE_M - TILE0)
#define ROWHALF (TILE0 * 128)  // 25088

__device__ int    g_deg   [M_PAD];     // zero at entry; restored by k_scan1
__device__ int    g_rowptr[M_PAD + 1];
__device__ int    g_rank  [E_MAX];     // edge rank within its destination
__device__ int    g_esrc  [E_MAX];
__device__ int    g_bsum  [64];
__device__ float  g_dinv  [M_PAD];
__device__ __half g_xh    [M_PAD * D0];  // xs = x * dinv, fp16 (hop-1 src)
__device__ __half g_gsh   [M_PAD * D2];  // (H1 @ W2) * dinv, fp16 (hop-2 src)
__device__ __half g_ah    [M_PAD * D0];  // hop-1 result (GEMM1 A), fp16
__device__ __half g_h1h   [M_PAD * D0];  // relu(..) (GEMM2 A), fp16
__device__ __half g_w1    [D0 * D0];     // W1^T [n][k] fp16
__device__ __half g_w2    [D2 * D0];     // W2^T [n][k] fp16

__global__ void k_noop() {}

// --------------------------- setup: deg histogram (+rank) + weight cvt ------

__global__ void k_deg_wsplit(const int* __restrict__ dst, int E,
                             const float* __restrict__ W1,
                             const float* __restrict__ W2, int nDegBlocks) {
    if ((int)blockIdx.x < nDegBlocks) {
        int base = blockIdx.x * 1024 + threadIdx.x;
#pragma unroll
        for (int u = 0; u < 4; u++) {
            int i = base + u * 256;
            if (i < E) {
                int d = __ldg(&dst[i]);
                g_rank[i] = atomicAdd(&g_deg[d], 1);
            }
        }
    } else {
        int i = (blockIdx.x - nDegBlocks) * 256 + threadIdx.x;
        if (i < D0 * D0) {
            int n = i >> 8, k = i & 255;
            g_w1[n * D0 + k] = __float2half_rn(W1[k * D0 + n]);
        } else if (i < D0 * D0 + D2 * D0) {
            int j = i - D0 * D0;
            int n = j >> 8, k = j & 255;
            g_w2[n * D0 + k] = __float2half_rn(W2[k * D2 + n]);
        }
    }
}

// fused: read deg, zero deg (restore invariant), compute dinv, block scan
__global__ void __launch_bounds__(1024) k_scan1() {
    __shared__ int warp_red[32];
    const int tid = threadIdx.x, lane = tid & 31, wid = tid >> 5;
    int idx = blockIdx.x * 1024 + tid;
    int v = 0;
    if (idx < M_PAD) {
        v = g_deg[idx];
        g_deg[idx] = 0;
        g_dinv[idx] = (idx < N_NODES) ? rsqrtf((float)(v + 1)) : 0.0f;
    }
    int inc = v;
#pragma unroll
    for (int off = 1; off < 32; off <<= 1) {
        int t = __shfl_up_sync(0xffffffff, inc, off);
        if (lane >= off) inc += t;
    }
    if (lane == 31) warp_red[wid] = inc;
    __syncthreads();
    if (wid == 0) {
        int w = warp_red[lane];
#pragma unroll
        for (int off = 1; off < 32; off <<= 1) {
            int t = __shfl_up_sync(0xffffffff, w, off);
            if (lane >= off) w += t;
        }
        warp_red[lane] = w;
    }
    __syncthreads();
    int excl = ((wid > 0) ? warp_red[wid - 1] : 0) + (inc - v);
    if (idx < M_PAD) g_rowptr[idx] = excl;
    if (tid == 1023) g_bsum[blockIdx.x] = warp_red[31];
}

// apply block offsets (computes own prefix of g_bsum; max 64 blocks)
__global__ void __launch_bounds__(1024) k_scan3(int E) {
    __shared__ int s_off;
    if (threadIdx.x < 32) {
        int b = blockIdx.x;
        int v = 0;
        if ((int)threadIdx.x < b) v = g_bsum[threadIdx.x];
        if ((int)threadIdx.x + 32 < b) v += g_bsum[threadIdx.x + 32];
#pragma unroll
        for (int off = 16; off > 0; off >>= 1)
            v += __shfl_down_sync(0xffffffff, v, off);
        if (threadIdx.x == 0) s_off = v;
    }
    __syncthreads();
    int idx = blockIdx.x * 1024 + threadIdx.x;
    if (idx < M_PAD) {
        g_rowptr[idx] += s_off;
    } else if (idx == M_PAD) {
        g_rowptr[M_PAD] = E;
    }
}

// atomic-free fill: pos = rowptr[dst] + rank
__global__ void k_fill(const int* __restrict__ src, const int* __restrict__ dst, int E) {
    int base = blockIdx.x * 1024 + threadIdx.x;
#pragma unroll
    for (int u = 0; u < 4; u++) {
        int i = base + u * 256;
        if (i < E) {
            int d = __ldg(&dst[i]);
            int r = __ldg(&g_rank[i]);
            g_esrc[__ldg(&g_rowptr[d]) + r] = __ldg(&src[i]);
        }
    }
}

// --------------------------- xs = x*dinv (fp16) ------------------------------

__global__ void k_scale_h(const float* __restrict__ x) {
    int i = blockIdx.x * blockDim.x + threadIdx.x;      // float4 index
    if (i >= M_PAD * (D0 / 4)) return;
    int row = i >> 6;
    float4 v = make_float4(0.f, 0.f, 0.f, 0.f);
    if (row < N_NODES) {
        v = ((const float4*)x)[i];
        float s = g_dinv[row];
        v.x *= s; v.y *= s; v.z *= s; v.w *= s;
    }
    __half2 h0 = __floats2half2_rn(v.x, v.y);
    __half2 h1 = __floats2half2_rn(v.z, v.w);
    uint2 o;
    o.x = *reinterpret_cast<uint32_t*>(&h0);
    o.y = *reinterpret_cast<uint32_t*>(&h1);
    ((uint2*)g_xh)[i] = o;
}

// --------------------------- helpers -----------------------------------------

__device__ __forceinline__ uint32_t packh2(float a, float b) {
    __half2 h = __floats2half2_rn(a, b);
    return *reinterpret_cast<uint32_t*>(&h);
}
__device__ __forceinline__ void acc8(float* a, uint4 v) {
    const __half2* h = reinterpret_cast<const __half2*>(&v);
    float2 f0 = __half22float2(h[0]);
    float2 f1 = __half22float2(h[1]);
    float2 f2 = __half22float2(h[2]);
    float2 f3 = __half22float2(h[3]);
    a[0] += f0.x; a[1] += f0.y; a[2] += f1.x; a[3] += f1.y;
    a[4] += f2.x; a[5] += f2.y; a[6] += f3.x; a[7] += f3.y;
}
__device__ __forceinline__ void acc4(float* a, uint2 v) {
    const __half2* h = reinterpret_cast<const __half2*>(&v);
    float2 f0 = __half22float2(h[0]);
    float2 f1 = __half22float2(h[1]);
    a[0] += f0.x; a[1] += f0.y; a[2] += f1.x; a[3] += f1.y;
}

// --------------------------- gathers ----------------------------------------

// hop-1 gather over rows [rowBeg, rowEnd): warp per dst row; lane owns 8 elems.
__global__ void __launch_bounds__(256) k_gather256(int rowBeg, int rowEnd) {
    int w = rowBeg + ((blockIdx.x * blockDim.x + threadIdx.x) >> 5);
    if (w >= rowEnd) return;
    const int lane = threadIdx.x & 31;
    float a[8];
#pragma unroll
    for (int j = 0; j < 8; j++) a[j] = 0.f;
    if (w < N_NODES) {
        const uint4* xh = (const uint4*)g_xh;   // row stride 32 uint4
        acc8(a, __ldg(&xh[(size_t)w * 32 + lane]));   // self term
        int e   = __ldg(&g_rowptr[w]);
        int end = __ldg(&g_rowptr[w + 1]);
        for (; e + 3 < end; e += 4) {
            int s0 = __ldg(&g_esrc[e]);
            int s1 = __ldg(&g_esrc[e + 1]);
            int s2 = __ldg(&g_esrc[e + 2]);
            int s3 = __ldg(&g_esrc[e + 3]);
            uint4 v0 = __ldg(&xh[(size_t)s0 * 32 + lane]);
            uint4 v1 = __ldg(&xh[(size_t)s1 * 32 + lane]);
            uint4 v2 = __ldg(&xh[(size_t)s2 * 32 + lane]);
            uint4 v3 = __ldg(&xh[(size_t)s3 * 32 + lane]);
            acc8(a, v0); acc8(a, v1); acc8(a, v2); acc8(a, v3);
        }
        for (; e < end; e++) {
            int s0 = __ldg(&g_esrc[e]);
            acc8(a, __ldg(&xh[(size_t)s0 * 32 + lane]));
        }
        float sd = g_dinv[w];
#pragma unroll
        for (int j = 0; j < 8; j++) a[j] *= sd;
    }
    uint4 o;
    o.x = packh2(a[0], a[1]);
    o.y = packh2(a[2], a[3]);
    o.z = packh2(a[4], a[5]);
    o.w = packh2(a[6], a[7]);
    ((uint4*)g_ah)[(size_t)w * 32 + lane] = o;
}

// hop-2 gather, D=128 fp16 src: warp per dst row; lane owns 4 elements.
__global__ void __launch_bounds__(256) k_gather128(const float* __restrict__ b2,
                                                   float* __restrict__ out) {
    int w = (blockIdx.x * blockDim.x + threadIdx.x) >> 5;
    if (w >= N_NODES) return;
    const int lane = threadIdx.x & 31;
    const uint2* gs = (const uint2*)g_gsh;      // row stride 32 uint2
    float a[4] = {0.f, 0.f, 0.f, 0.f};
    acc4(a, __ldg(&gs[(size_t)w * 32 + lane]));
    int e   = __ldg(&g_rowptr[w]);
    int end = __ldg(&g_rowptr[w + 1]);
    for (; e + 3 < end; e += 4) {
        int s0 = __ldg(&g_esrc[e]);
        int s1 = __ldg(&g_esrc[e + 1]);
        int s2 = __ldg(&g_esrc[e + 2]);
        int s3 = __ldg(&g_esrc[e + 3]);
        uint2 v0 = __ldg(&gs[(size_t)s0 * 32 + lane]);
        uint2 v1 = __ldg(&gs[(size_t)s1 * 32 + lane]);
        uint2 v2 = __ldg(&gs[(size_t)s2 * 32 + lane]);
        uint2 v3 = __ldg(&gs[(size_t)s3 * 32 + lane]);
        acc4(a, v0); acc4(a, v1); acc4(a, v2); acc4(a, v3);
    }
    for (; e < end; e++) {
        int s0 = __ldg(&g_esrc[e]);
        acc4(a, __ldg(&gs[(size_t)s0 * 32 + lane]));
    }
    float s = g_dinv[w];
    float4 b = __ldg(&((const float4*)b2)[lane]);
    float4 o;
    o.x = a[0] * s + b.x;
    o.y = a[1] * s + b.y;
    o.z = a[2] * s + b.z;
    o.w = a[3] * s + b.w;
    ((float4*)out)[(size_t)w * 32 + lane] = o;
}

// --------------------------- HMMA GEMM (cp.async pipelined) -----------------
// C[128x128] tile of A[M_PAD,256](fp16) @ B^T, B [n][256] fp16.
// Single product, fp32 accum (mma.sync m16n8k16 f16).
// 8 warps (2x4), warp tile 64x32, BK=32, double-buffered dynamic smem.

__device__ __forceinline__ uint32_t smem_u32(const void* p) {
    return (uint32_t)__cvta_generic_to_shared(p);
}
__device__ __forceinline__ void cp16(uint32_t s, const void* g) {
    asm volatile("cp.async.cg.shared.global [%0], [%1], 16;" :: "r"(s), "l"(g));
}
#define CP_COMMIT() asm volatile("cp.async.commit_group;" ::: "memory")
#define CP_WAIT(n)  asm volatile("cp.async.wait_group %0;" :: "n"(n) : "memory")

__device__ __forceinline__ void ldsm_x4(uint32_t& r0, uint32_t& r1,
                                        uint32_t& r2, uint32_t& r3, uint32_t a) {
    asm volatile("ldmatrix.sync.aligned.m8n8.x4.shared.b16 {%0,%1,%2,%3}, [%4];"
                 : "=r"(r0), "=r"(r1), "=r"(r2), "=r"(r3) : "r"(a));
}
__device__ __forceinline__ void mma16816(float* d, const uint32_t* a, const uint32_t* b) {
    asm volatile(
        "mma.sync.aligned.m16n8k16.row.col.f32.f16.f16.f32 "
        "{%0,%1,%2,%3}, {%4,%5,%6,%7}, {%8,%9}, {%0,%1,%2,%3};"
        : "+f"(d[0]), "+f"(d[1]), "+f"(d[2]), "+f"(d[3])
        : "r"(a[0]), "r"(a[1]), "r"(a[2]), "r"(a[3]), "r"(b[0]), "r"(b[1]));
}

#define BK      32
#define LDS     40                     // padded row stride (elements)
#define BUFB    (128 * LDS * 2)        // 10240 bytes per tile buffer
#define SM_MMA  (4 * BUFB)             // 40960 bytes (2 stages x 2 buffers)

template<int MODE>
__global__ void __launch_bounds__(256)
k_mma(const float* __restrict__ bias, int tileOff) {
    extern __shared__ char dynsmem[];
    const uint32_t sb = smem_u32(dynsmem);

    const int tid  = threadIdx.x;
    const int lane = tid & 31;
    const int wy   = (tid >> 5) & 1;
    const int wx   = (tid >> 5) >> 1;
    const size_t rowBase = (size_t)(tileOff + blockIdx.y) * 128;
    const int    colBase = blockIdx.x * 128;

    const __half* A = (MODE == 1) ? g_ah : g_h1h;
    const __half* B = (MODE == 1) ? g_w1 : g_w2;

    float acc[4][4][4];
#pragma unroll
    for (int i = 0; i < 4; i++)
#pragma unroll
        for (int j = 0; j < 4; j++)
#pragma unroll
            for (int k = 0; k < 4; k++) acc[i][j][k] = 0.f;

    const int fr = tid >> 1;
    const int fh = (tid & 1) * 16;
    const size_t gA = (rowBase + fr) * 256 + fh;
    const size_t gB = ((size_t)colBase + fr) * 256 + fh;
    const uint32_t dOff = (uint32_t)((fr * LDS + fh) * 2);

    const uint32_t aoff = (uint32_t)(((wy * 64 + (lane & 15)) * LDS + (lane >> 4) * 8) * 2);
    const uint32_t boff = (uint32_t)(((wx * 32 + (lane & 7) + ((lane >> 4) << 3)) * LDS
                                      + (((lane >> 3) & 1) * 8)) * 2);

    auto issue = [&](int kc, int st) {
        const int k0 = kc * BK;
        uint32_t b = sb + (uint32_t)st * (2 * BUFB);
        cp16(b + dOff,      A + gA + k0);
        cp16(b + dOff + 16, A + gA + k0 + 8);
        b += BUFB;
        cp16(b + dOff,      B + gB + k0);
        cp16(b + dOff + 16, B + gB + k0 + 8);
    };

    issue(0, 0);
    CP_COMMIT();

#pragma unroll 1
    for (int kc = 0; kc < 8; kc++) {
        const int cur = kc & 1;
        if (kc < 7) {
            issue(kc + 1, cur ^ 1);
            CP_COMMIT();
            CP_WAIT(1);
        } else {
            CP_WAIT(0);
        }
        __syncthreads();

        const uint32_t sA_b = sb + (uint32_t)cur * (2 * BUFB);
        const uint32_t sB_b = sA_b + BUFB;

#pragma unroll
        for (int ks = 0; ks < 2; ks++) {
            const uint32_t kb = ks * 32;
            uint32_t a[4][4], bh[2][4];
#pragma unroll
            for (int mi = 0; mi < 4; mi++) {
                uint32_t off = aoff + mi * (16 * LDS * 2) + kb;
                ldsm_x4(a[mi][0], a[mi][1], a[mi][2], a[mi][3], sA_b + off);
            }
#pragma unroll
            for (int p = 0; p < 2; p++) {
                uint32_t off = boff + p * (16 * LDS * 2) + kb;
                ldsm_x4(bh[p][0], bh[p][1], bh[p][2], bh[p][3], sB_b + off);
            }
#pragma unroll
            for (int mi = 0; mi < 4; mi++)
#pragma unroll
                for (int ni = 0; ni < 4; ni++) {
                    const int p = ni >> 1, q = (ni & 1) * 2;
                    uint32_t b0[2] = { bh[p][q], bh[p][q + 1] };
                    mma16816(acc[mi][ni], a[mi], b0);
                }
        }
        __syncthreads();
    }

    const int gid = lane >> 2, tig = lane & 3;
#pragma unroll
    for (int mi = 0; mi < 4; mi++) {
        const int row = (int)rowBase + wy * 64 + mi * 16 + gid;
#pragma unroll
        for (int ni = 0; ni < 4; ni++) {
            const int col = colBase + wx * 32 + ni * 8 + tig * 2;
            float d0 = acc[mi][ni][0], d1 = acc[mi][ni][1];
            float d2 = acc[mi][ni][2], d3 = acc[mi][ni][3];
            if (MODE == 1) {
                float b0 = __ldg(&bias[col]), b1 = __ldg(&bias[col + 1]);
                float v0 = fmaxf(d0 + b0, 0.f), v1 = fmaxf(d1 + b1, 0.f);
                float v2 = fmaxf(d2 + b0, 0.f), v3 = fmaxf(d3 + b1, 0.f);
                *(uint32_t*)(g_h1h + (size_t)row * 256 + col)       = packh2(v0, v1);
                *(uint32_t*)(g_h1h + (size_t)(row + 8) * 256 + col) = packh2(v2, v3);
            } else {
                float s0 = g_dinv[row], s1 = g_dinv[row + 8];
                *(uint32_t*)(g_gsh + (size_t)row * 128 + col)       = packh2(d0 * s0, d1 * s0);
                *(uint32_t*)(g_gsh + (size_t)(row + 8) * 128 + col) = packh2(d2 * s1, d3 * s1);
            }
        }
    }
}

// ---------------------------------------------------------------------------

struct HxCtx {
    cudaStream_t s2 = nullptr;
    cudaEvent_t evScale = nullptr, evG0 = nullptr, evM0 = nullptr, evFork = nullptr;
    bool ok = false;
    void init() {
        if (cudaStreamCreateWithFlags(&s2, cudaStreamNonBlocking) != cudaSuccess) return;
        cudaEventCreateWithFlags(&evScale, cudaEventDisableTiming);
        cudaEventCreateWithFlags(&evG0, cudaEventDisableTiming);
        cudaEventCreateWithFlags(&evM0, cudaEventDisableTiming);
        cudaEventCreateWithFlags(&evFork, cudaEventDisableTiming);
        cudaFuncSetAttribute(k_mma<1>, cudaFuncAttributeMaxDynamicSharedMemorySize, SM_MMA);
        cudaFuncSetAttribute(k_mma<2>, cudaFuncAttributeMaxDynamicSharedMemorySize, SM_MMA);
        k_noop<<<1, 32>>>();
        k_noop<<<1, 32, 0, s2>>>();
        cudaStreamSynchronize(s2);
        cudaStreamSynchronize(0);
        ok = true;
    }
};

extern "C" void kernel_launch(void* const* d_in, const int* in_sizes, int n_in,
                              void* d_out, int out_size) {
    const float* x  = (const float*)d_in[0];
    const int*   ei = (const int*)  d_in[1];
    const float* W1 = (const float*)d_in[2];
    const float* b1 = (const float*)d_in[3];
    const float* W2 = (const float*)d_in[4];
    const float* b2 = (const float*)d_in[5];
    float* out = (float*)d_out;

    const int E = in_sizes[1] / 2;
    const int* src = ei;
    const int* dst = ei + E;
    const int nb = (M_PAD + 1023) / 1024;              // 49
    const int nDegBlocks = (E + 1023) / 1024;
    const int nSplitBlocks = (D0 * D0 + D2 * D0 + 255) / 256;

    static HxCtx ctx;
    cudaStreamCaptureStatus cap = cudaStreamCaptureStatusNone;
    cudaStreamIsCapturing(0, &cap);
    if (!ctx.ok && cap == cudaStreamCaptureStatusNone) ctx.init();
    if (!ctx.ok) {
        cudaFuncSetAttribute(k_mma<1>, cudaFuncAttributeMaxDynamicSharedMemorySize, SM_MMA);
        cudaFuncSetAttribute(k_mma<2>, cudaFuncAttributeMaxDynamicSharedMemorySize, SM_MMA);
    }

    if (ctx.ok) {
        cudaStream_t s2 = ctx.s2;

        k_deg_wsplit<<<nDegBlocks + nSplitBlocks, 256>>>(dst, E, W1, W2, nDegBlocks);
        k_scan1<<<nb, 1024>>>();
        cudaEventRecord(ctx.evFork, 0);

        // s2: scale_h (needs dinv only) overlaps scan3+fill
        cudaStreamWaitEvent(s2, ctx.evFork, 0);
        k_scale_h<<<(M_PAD * (D0 / 4) + 255) / 256, 256, 0, s2>>>(x);
        cudaEventRecord(ctx.evScale, s2);

        k_scan3<<<nb, 1024>>>(E);
        k_fill<<<(E + 1023) / 1024, 256>>>(src, dst, E);
        cudaStreamWaitEvent(0, ctx.evScale, 0);

        // chunk 0 gather, then fork its GEMMs to s2 while chunk 1 gathers
        k_gather256<<<(ROWHALF * 32 + 255) / 256, 256>>>(0, ROWHALF);
        cudaEventRecord(ctx.evG0, 0);

        cudaStreamWaitEvent(s2, ctx.evG0, 0);
        k_mma<1><<<dim3(2, TILE0), 256, SM_MMA, s2>>>(b1, 0);
        k_mma<2><<<dim3(1, TILE0), 256, SM_MMA, s2>>>(nullptr, 0);
        cudaEventRecord(ctx.evM0, s2);

        k_gather256<<<((M_PAD - ROWHALF) * 32 + 255) / 256, 256>>>(ROWHALF, M_PAD);
        k_mma<1><<<dim3(2, TILE1), 256, SM_MMA>>>(b1, TILE0);
        k_mma<2><<<dim3(1, TILE1), 256, SM_MMA>>>(nullptr, TILE0);

        cudaStreamWaitEvent(0, ctx.evM0, 0);
        k_gather128<<<(N_NODES * 32 + 255) / 256, 256>>>(b2, out);
    } else {
        // serial fallback
        k_deg_wsplit<<<nDegBlocks + nSplitBlocks, 256>>>(dst, E, W1, W2, nDegBlocks);
        k_scan1<<<nb, 1024>>>();
        k_scan3<<<nb, 1024>>>(E);
        k_fill<<<(E + 1023) / 1024, 256>>>(src, dst, E);
        k_scale_h<<<(M_PAD * (D0 / 4) + 255) / 256, 256>>>(x);
        k_gather256<<<(M_PAD * 32 + 255) / 256, 256>>>(0, M_PAD);
        k_mma<1><<<dim3(2, NTILE_M), 256, SM_MMA>>>(b1, 0);
        k_mma<2><<<dim3(1, NTILE_M), 256, SM_MMA>>>(nullptr, 0);
        k_gather128<<<(N_NODES * 32 + 255) / 256, 256>>>(b2, out);
    }
}

// round 17
// speedup vs baseline: 1.0187x; 1.0081x over previous
#include <cuda_runtime.h>
#include <cuda_fp16.h>
#include <cstdint>

// ---------------------------------------------------------------------------
// SGCEncoder: out = prop(relu(prop(x) @ W1 + b1)) @ W2 + b2
//   prop = D^-1/2 (A+I) D^-1/2
// Rewrites:
//   prop(x)[d] = dinv[d] * ( sum_{s->d} xs[s] + xs[d] ),  xs = x*dinv (fp16)
//   prop(H1) @ W2 = prop(H1 @ W2)          (propagate at D=128, fp16 source)
// FINAL: measured-best configuration (197.1us).
//   - CSR-by-dst via rank trick (atomic-free fill)
//   - fp16 gather sources both hops, fp32 accumulation
//   - fp16 single-product cp.async-pipelined HMMA GEMMs
//   - stream-forked scale_h + chunk-0 GEMM overlap
// ---------------------------------------------------------------------------

#define N_NODES 50000
#define M_PAD   50048          // 391 * 128
#define D0      256
#define D2      128
#define E_MAX   1600000
#define NTILE_M 391
#define TILE0   196            // chunk0 tiles
#define TILE1   (NTILE_M - TILE0)
#define ROWHALF (TILE0 * 128)  // 25088

__device__ int    g_deg   [M_PAD];     // zero at entry; restored by k_scan1
__device__ int    g_rowptr[M_PAD + 1];
__device__ int    g_rank  [E_MAX];     // edge rank within its destination
__device__ int    g_esrc  [E_MAX];
__device__ int    g_bsum  [64];
__device__ float  g_dinv  [M_PAD];
__device__ __half g_xh    [M_PAD * D0];  // xs = x * dinv, fp16 (hop-1 src)
__device__ __half g_gsh   [M_PAD * D2];  // (H1 @ W2) * dinv, fp16 (hop-2 src)
__device__ __half g_ah    [M_PAD * D0];  // hop-1 result (GEMM1 A), fp16
__device__ __half g_h1h   [M_PAD * D0];  // relu(..) (GEMM2 A), fp16
__device__ __half g_w1    [D0 * D0];     // W1^T [n][k] fp16
__device__ __half g_w2    [D2 * D0];     // W2^T [n][k] fp16

__global__ void k_noop() {}

// --------------------------- setup: deg histogram (+rank) + weight cvt ------

__global__ void k_deg_wsplit(const int* __restrict__ dst, int E,
                             const float* __restrict__ W1,
                             const float* __restrict__ W2, int nDegBlocks) {
    if ((int)blockIdx.x < nDegBlocks) {
        int base = blockIdx.x * 1024 + threadIdx.x;
#pragma unroll
        for (int u = 0; u < 4; u++) {
            int i = base + u * 256;
            if (i < E) {
                int d = __ldg(&dst[i]);
                g_rank[i] = atomicAdd(&g_deg[d], 1);
            }
        }
    } else {
        int i = (blockIdx.x - nDegBlocks) * 256 + threadIdx.x;
        if (i < D0 * D0) {
            int n = i >> 8, k = i & 255;
            g_w1[n * D0 + k] = __float2half_rn(W1[k * D0 + n]);
        } else if (i < D0 * D0 + D2 * D0) {
            int j = i - D0 * D0;
            int n = j >> 8, k = j & 255;
            g_w2[n * D0 + k] = __float2half_rn(W2[k * D2 + n]);
        }
    }
}

// fused: read deg, zero deg (restore invariant), compute dinv, block scan
__global__ void __launch_bounds__(1024) k_scan1() {
    __shared__ int warp_red[32];
    const int tid = threadIdx.x, lane = tid & 31, wid = tid >> 5;
    int idx = blockIdx.x * 1024 + tid;
    int v = 0;
    if (idx < M_PAD) {
        v = g_deg[idx];
        g_deg[idx] = 0;
        g_dinv[idx] = (idx < N_NODES) ? rsqrtf((float)(v + 1)) : 0.0f;
    }
    int inc = v;
#pragma unroll
    for (int off = 1; off < 32; off <<= 1) {
        int t = __shfl_up_sync(0xffffffff, inc, off);
        if (lane >= off) inc += t;
    }
    if (lane == 31) warp_red[wid] = inc;
    __syncthreads();
    if (wid == 0) {
        int w = warp_red[lane];
#pragma unroll
        for (int off = 1; off < 32; off <<= 1) {
            int t = __shfl_up_sync(0xffffffff, w, off);
            if (lane >= off) w += t;
        }
        warp_red[lane] = w;
    }
    __syncthreads();
    int excl = ((wid > 0) ? warp_red[wid - 1] : 0) + (inc - v);
    if (idx < M_PAD) g_rowptr[idx] = excl;
    if (tid == 1023) g_bsum[blockIdx.x] = warp_red[31];
}

// apply block offsets (computes own prefix of g_bsum; max 64 blocks)
__global__ void __launch_bounds__(1024) k_scan3(int E) {
    __shared__ int s_off;
    if (threadIdx.x < 32) {
        int b = blockIdx.x;
        int v = 0;
        if ((int)threadIdx.x < b) v = g_bsum[threadIdx.x];
        if ((int)threadIdx.x + 32 < b) v += g_bsum[threadIdx.x + 32];
#pragma unroll
        for (int off = 16; off > 0; off >>= 1)
            v += __shfl_down_sync(0xffffffff, v, off);
        if (threadIdx.x == 0) s_off = v;
    }
    __syncthreads();
    int idx = blockIdx.x * 1024 + threadIdx.x;
    if (idx < M_PAD) {
        g_rowptr[idx] += s_off;
    } else if (idx == M_PAD) {
        g_rowptr[M_PAD] = E;
    }
}

// atomic-free fill: pos = rowptr[dst] + rank
__global__ void k_fill(const int* __restrict__ src, const int* __restrict__ dst, int E) {
    int base = blockIdx.x * 1024 + threadIdx.x;
#pragma unroll
    for (int u = 0; u < 4; u++) {
        int i = base + u * 256;
        if (i < E) {
            int d = __ldg(&dst[i]);
            int r = __ldg(&g_rank[i]);
            g_esrc[__ldg(&g_rowptr[d]) + r] = __ldg(&src[i]);
        }
    }
}

// --------------------------- xs = x*dinv (fp16) ------------------------------

__global__ void k_scale_h(const float* __restrict__ x) {
    int i = blockIdx.x * blockDim.x + threadIdx.x;      // float4 index
    if (i >= M_PAD * (D0 / 4)) return;
    int row = i >> 6;
    float4 v = make_float4(0.f, 0.f, 0.f, 0.f);
    if (row < N_NODES) {
        v = ((const float4*)x)[i];
        float s = g_dinv[row];
        v.x *= s; v.y *= s; v.z *= s; v.w *= s;
    }
    __half2 h0 = __floats2half2_rn(v.x, v.y);
    __half2 h1 = __floats2half2_rn(v.z, v.w);
    uint2 o;
    o.x = *reinterpret_cast<uint32_t*>(&h0);
    o.y = *reinterpret_cast<uint32_t*>(&h1);
    ((uint2*)g_xh)[i] = o;
}

// --------------------------- helpers -----------------------------------------

__device__ __forceinline__ uint32_t packh2(float a, float b) {
    __half2 h = __floats2half2_rn(a, b);
    return *reinterpret_cast<uint32_t*>(&h);
}
__device__ __forceinline__ void acc8(float* a, uint4 v) {
    const __half2* h = reinterpret_cast<const __half2*>(&v);
    float2 f0 = __half22float2(h[0]);
    float2 f1 = __half22float2(h[1]);
    float2 f2 = __half22float2(h[2]);
    float2 f3 = __half22float2(h[3]);
    a[0] += f0.x; a[1] += f0.y; a[2] += f1.x; a[3] += f1.y;
    a[4] += f2.x; a[5] += f2.y; a[6] += f3.x; a[7] += f3.y;
}
__device__ __forceinline__ void acc4(float* a, uint2 v) {
    const __half2* h = reinterpret_cast<const __half2*>(&v);
    float2 f0 = __half22float2(h[0]);
    float2 f1 = __half22float2(h[1]);
    a[0] += f0.x; a[1] += f0.y; a[2] += f1.x; a[3] += f1.y;
}

// --------------------------- gathers ----------------------------------------

// hop-1 gather over rows [rowBeg, rowEnd): warp per dst row; lane owns 8 elems.
__global__ void __launch_bounds__(256) k_gather256(int rowBeg, int rowEnd) {
    int w = rowBeg + ((blockIdx.x * blockDim.x + threadIdx.x) >> 5);
    if (w >= rowEnd) return;
    const int lane = threadIdx.x & 31;
    float a[8];
#pragma unroll
    for (int j = 0; j < 8; j++) a[j] = 0.f;
    if (w < N_NODES) {
        const uint4* xh = (const uint4*)g_xh;   // row stride 32 uint4
        acc8(a, __ldg(&xh[(size_t)w * 32 + lane]));   // self term
        int e   = __ldg(&g_rowptr[w]);
        int end = __ldg(&g_rowptr[w + 1]);
        for (; e + 3 < end; e += 4) {
            int s0 = __ldg(&g_esrc[e]);
            int s1 = __ldg(&g_esrc[e + 1]);
            int s2 = __ldg(&g_esrc[e + 2]);
            int s3 = __ldg(&g_esrc[e + 3]);
            uint4 v0 = __ldg(&xh[(size_t)s0 * 32 + lane]);
            uint4 v1 = __ldg(&xh[(size_t)s1 * 32 + lane]);
            uint4 v2 = __ldg(&xh[(size_t)s2 * 32 + lane]);
            uint4 v3 = __ldg(&xh[(size_t)s3 * 32 + lane]);
            acc8(a, v0); acc8(a, v1); acc8(a, v2); acc8(a, v3);
        }
        for (; e < end; e++) {
            int s0 = __ldg(&g_esrc[e]);
            acc8(a, __ldg(&xh[(size_t)s0 * 32 + lane]));
        }
        float sd = g_dinv[w];
#pragma unroll
        for (int j = 0; j < 8; j++) a[j] *= sd;
    }
    uint4 o;
    o.x = packh2(a[0], a[1]);
    o.y = packh2(a[2], a[3]);
    o.z = packh2(a[4], a[5]);
    o.w = packh2(a[6], a[7]);
    ((uint4*)g_ah)[(size_t)w * 32 + lane] = o;
}

// hop-2 gather, D=128 fp16 src: warp per dst row; lane owns 4 elements.
__global__ void __launch_bounds__(256) k_gather128(const float* __restrict__ b2,
                                                   float* __restrict__ out) {
    int w = (blockIdx.x * blockDim.x + threadIdx.x) >> 5;
    if (w >= N_NODES) return;
    const int lane = threadIdx.x & 31;
    const uint2* gs = (const uint2*)g_gsh;      // row stride 32 uint2
    float a[4] = {0.f, 0.f, 0.f, 0.f};
    acc4(a, __ldg(&gs[(size_t)w * 32 + lane]));
    int e   = __ldg(&g_rowptr[w]);
    int end = __ldg(&g_rowptr[w + 1]);
    for (; e + 3 < end; e += 4) {
        int s0 = __ldg(&g_esrc[e]);
        int s1 = __ldg(&g_esrc[e + 1]);
        int s2 = __ldg(&g_esrc[e + 2]);
        int s3 = __ldg(&g_esrc[e + 3]);
        uint2 v0 = __ldg(&gs[(size_t)s0 * 32 + lane]);
        uint2 v1 = __ldg(&gs[(size_t)s1 * 32 + lane]);
        uint2 v2 = __ldg(&gs[(size_t)s2 * 32 + lane]);
        uint2 v3 = __ldg(&gs[(size_t)s3 * 32 + lane]);
        acc4(a, v0); acc4(a, v1); acc4(a, v2); acc4(a, v3);
    }
    for (; e < end; e++) {
        int s0 = __ldg(&g_esrc[e]);
        acc4(a, __ldg(&gs[(size_t)s0 * 32 + lane]));
    }
    float s = g_dinv[w];
    float4 b = __ldg(&((const float4*)b2)[lane]);
    float4 o;
    o.x = a[0] * s + b.x;
    o.y = a[1] * s + b.y;
    o.z = a[2] * s + b.z;
    o.w = a[3] * s + b.w;
    ((float4*)out)[(size_t)w * 32 + lane] = o;
}

// --------------------------- HMMA GEMM (cp.async pipelined) -----------------
// C[128x128] tile of A[M_PAD,256](fp16) @ B^T, B [n][256] fp16.
// Single product, fp32 accum (mma.sync m16n8k16 f16).
// 8 warps (2x4), warp tile 64x32, BK=32, double-buffered dynamic smem.

__device__ __forceinline__ uint32_t smem_u32(const void* p) {
    return (uint32_t)__cvta_generic_to_shared(p);
}
__device__ __forceinline__ void cp16(uint32_t s, const void* g) {
    asm volatile("cp.async.cg.shared.global [%0], [%1], 16;" :: "r"(s), "l"(g));
}
#define CP_COMMIT() asm volatile("cp.async.commit_group;" ::: "memory")
#define CP_WAIT(n)  asm volatile("cp.async.wait_group %0;" :: "n"(n) : "memory")

__device__ __forceinline__ void ldsm_x4(uint32_t& r0, uint32_t& r1,
                                        uint32_t& r2, uint32_t& r3, uint32_t a) {
    asm volatile("ldmatrix.sync.aligned.m8n8.x4.shared.b16 {%0,%1,%2,%3}, [%4];"
                 : "=r"(r0), "=r"(r1), "=r"(r2), "=r"(r3) : "r"(a));
}
__device__ __forceinline__ void mma16816(float* d, const uint32_t* a, const uint32_t* b) {
    asm volatile(
        "mma.sync.aligned.m16n8k16.row.col.f32.f16.f16.f32 "
        "{%0,%1,%2,%3}, {%4,%5,%6,%7}, {%8,%9}, {%0,%1,%2,%3};"
        : "+f"(d[0]), "+f"(d[1]), "+f"(d[2]), "+f"(d[3])
        : "r"(a[0]), "r"(a[1]), "r"(a[2]), "r"(a[3]), "r"(b[0]), "r"(b[1]));
}

#define BK      32
#define LDS     40                     // padded row stride (elements)
#define BUFB    (128 * LDS * 2)        // 10240 bytes per tile buffer
#define SM_MMA  (4 * BUFB)             // 40960 bytes (2 stages x 2 buffers)

template<int MODE>
__global__ void __launch_bounds__(256)
k_mma(const float* __restrict__ bias, int tileOff) {
    extern __shared__ char dynsmem[];
    const uint32_t sb = smem_u32(dynsmem);

    const int tid  = threadIdx.x;
    const int lane = tid & 31;
    const int wy   = (tid >> 5) & 1;
    const int wx   = (tid >> 5) >> 1;
    const size_t rowBase = (size_t)(tileOff + blockIdx.y) * 128;
    const int    colBase = blockIdx.x * 128;

    const __half* A = (MODE == 1) ? g_ah : g_h1h;
    const __half* B = (MODE == 1) ? g_w1 : g_w2;

    float acc[4][4][4];
#pragma unroll
    for (int i = 0; i < 4; i++)
#pragma unroll
        for (int j = 0; j < 4; j++)
#pragma unroll
            for (int k = 0; k < 4; k++) acc[i][j][k] = 0.f;

    const int fr = tid >> 1;
    const int fh = (tid & 1) * 16;
    const size_t gA = (rowBase + fr) * 256 + fh;
    const size_t gB = ((size_t)colBase + fr) * 256 + fh;
    const uint32_t dOff = (uint32_t)((fr * LDS + fh) * 2);

    const uint32_t aoff = (uint32_t)(((wy * 64 + (lane & 15)) * LDS + (lane >> 4) * 8) * 2);
    const uint32_t boff = (uint32_t)(((wx * 32 + (lane & 7) + ((lane >> 4) << 3)) * LDS
                                      + (((lane >> 3) & 1) * 8)) * 2);

    auto issue = [&](int kc, int st) {
        const int k0 = kc * BK;
        uint32_t b = sb + (uint32_t)st * (2 * BUFB);
        cp16(b + dOff,      A + gA + k0);
        cp16(b + dOff + 16, A + gA + k0 + 8);
        b += BUFB;
        cp16(b + dOff,      B + gB + k0);
        cp16(b + dOff + 16, B + gB + k0 + 8);
    };

    issue(0, 0);
    CP_COMMIT();

#pragma unroll 1
    for (int kc = 0; kc < 8; kc++) {
        const int cur = kc & 1;
        if (kc < 7) {
            issue(kc + 1, cur ^ 1);
            CP_COMMIT();
            CP_WAIT(1);
        } else {
            CP_WAIT(0);
        }
        __syncthreads();

        const uint32_t sA_b = sb + (uint32_t)cur * (2 * BUFB);
        const uint32_t sB_b = sA_b + BUFB;

#pragma unroll
        for (int ks = 0; ks < 2; ks++) {
            const uint32_t kb = ks * 32;
            uint32_t a[4][4], bh[2][4];
#pragma unroll
            for (int mi = 0; mi < 4; mi++) {
                uint32_t off = aoff + mi * (16 * LDS * 2) + kb;
                ldsm_x4(a[mi][0], a[mi][1], a[mi][2], a[mi][3], sA_b + off);
            }
#pragma unroll
            for (int p = 0; p < 2; p++) {
                uint32_t off = boff + p * (16 * LDS * 2) + kb;
                ldsm_x4(bh[p][0], bh[p][1], bh[p][2], bh[p][3], sB_b + off);
            }
#pragma unroll
            for (int mi = 0; mi < 4; mi++)
#pragma unroll
                for (int ni = 0; ni < 4; ni++) {
                    const int p = ni >> 1, q = (ni & 1) * 2;
                    uint32_t b0[2] = { bh[p][q], bh[p][q + 1] };
                    mma16816(acc[mi][ni], a[mi], b0);
                }
        }
        __syncthreads();
    }

    const int gid = lane >> 2, tig = lane & 3;
#pragma unroll
    for (int mi = 0; mi < 4; mi++) {
        const int row = (int)rowBase + wy * 64 + mi * 16 + gid;
#pragma unroll
        for (int ni = 0; ni < 4; ni++) {
            const int col = colBase + wx * 32 + ni * 8 + tig * 2;
            float d0 = acc[mi][ni][0], d1 = acc[mi][ni][1];
            float d2 = acc[mi][ni][2], d3 = acc[mi][ni][3];
            if (MODE == 1) {
                float b0 = __ldg(&bias[col]), b1 = __ldg(&bias[col + 1]);
                float v0 = fmaxf(d0 + b0, 0.f), v1 = fmaxf(d1 + b1, 0.f);
                float v2 = fmaxf(d2 + b0, 0.f), v3 = fmaxf(d3 + b1, 0.f);
                *(uint32_t*)(g_h1h + (size_t)row * 256 + col)       = packh2(v0, v1);
                *(uint32_t*)(g_h1h + (size_t)(row + 8) * 256 + col) = packh2(v2, v3);
            } else {
                float s0 = g_dinv[row], s1 = g_dinv[row + 8];
                *(uint32_t*)(g_gsh + (size_t)row * 128 + col)       = packh2(d0 * s0, d1 * s0);
                *(uint32_t*)(g_gsh + (size_t)(row + 8) * 128 + col) = packh2(d2 * s1, d3 * s1);
            }
        }
    }
}

// ---------------------------------------------------------------------------

struct HxCtx {
    cudaStream_t s2 = nullptr;
    cudaEvent_t evScale = nullptr, evG0 = nullptr, evM0 = nullptr, evFork = nullptr;
    bool ok = false;
    void init() {
        if (cudaStreamCreateWithFlags(&s2, cudaStreamNonBlocking) != cudaSuccess) return;
        cudaEventCreateWithFlags(&evScale, cudaEventDisableTiming);
        cudaEventCreateWithFlags(&evG0, cudaEventDisableTiming);
        cudaEventCreateWithFlags(&evM0, cudaEventDisableTiming);
        cudaEventCreateWithFlags(&evFork, cudaEventDisableTiming);
        cudaFuncSetAttribute(k_mma<1>, cudaFuncAttributeMaxDynamicSharedMemorySize, SM_MMA);
        cudaFuncSetAttribute(k_mma<2>, cudaFuncAttributeMaxDynamicSharedMemorySize, SM_MMA);
        k_noop<<<1, 32>>>();
        k_noop<<<1, 32, 0, s2>>>();
        cudaStreamSynchronize(s2);
        cudaStreamSynchronize(0);
        ok = true;
    }
};

extern "C" void kernel_launch(void* const* d_in, const int* in_sizes, int n_in,
                              void* d_out, int out_size) {
    const float* x  = (const float*)d_in[0];
    const int*   ei = (const int*)  d_in[1];
    const float* W1 = (const float*)d_in[2];
    const float* b1 = (const float*)d_in[3];
    const float* W2 = (const float*)d_in[4];
    const float* b2 = (const float*)d_in[5];
    float* out = (float*)d_out;

    const int E = in_sizes[1] / 2;
    const int* src = ei;
    const int* dst = ei + E;
    const int nb = (M_PAD + 1023) / 1024;              // 49
    const int nDegBlocks = (E + 1023) / 1024;
    const int nSplitBlocks = (D0 * D0 + D2 * D0 + 255) / 256;

    static HxCtx ctx;
    cudaStreamCaptureStatus cap = cudaStreamCaptureStatusNone;
    cudaStreamIsCapturing(0, &cap);
    if (!ctx.ok && cap == cudaStreamCaptureStatusNone) ctx.init();
    if (!ctx.ok) {
        cudaFuncSetAttribute(k_mma<1>, cudaFuncAttributeMaxDynamicSharedMemorySize, SM_MMA);
        cudaFuncSetAttribute(k_mma<2>, cudaFuncAttributeMaxDynamicSharedMemorySize, SM_MMA);
    }

    if (ctx.ok) {
        cudaStream_t s2 = ctx.s2;

        k_deg_wsplit<<<nDegBlocks + nSplitBlocks, 256>>>(dst, E, W1, W2, nDegBlocks);
        k_scan1<<<nb, 1024>>>();
        cudaEventRecord(ctx.evFork, 0);

        // s2: scale_h (needs dinv only) overlaps scan3+fill
        cudaStreamWaitEvent(s2, ctx.evFork, 0);
        k_scale_h<<<(M_PAD * (D0 / 4) + 255) / 256, 256, 0, s2>>>(x);
        cudaEventRecord(ctx.evScale, s2);

        k_scan3<<<nb, 1024>>>(E);
        k_fill<<<(E + 1023) / 1024, 256>>>(src, dst, E);
        cudaStreamWaitEvent(0, ctx.evScale, 0);

        // chunk 0 gather, then fork its GEMMs to s2 while chunk 1 gathers
        k_gather256<<<(ROWHALF * 32 + 255) / 256, 256>>>(0, ROWHALF);
        cudaEventRecord(ctx.evG0, 0);

        cudaStreamWaitEvent(s2, ctx.evG0, 0);
        k_mma<1><<<dim3(2, TILE0), 256, SM_MMA, s2>>>(b1, 0);
        k_mma<2><<<dim3(1, TILE0), 256, SM_MMA, s2>>>(nullptr, 0);
        cudaEventRecord(ctx.evM0, s2);

        k_gather256<<<((M_PAD - ROWHALF) * 32 + 255) / 256, 256>>>(ROWHALF, M_PAD);
        k_mma<1><<<dim3(2, TILE1), 256, SM_MMA>>>(b1, TILE0);
        k_mma<2><<<dim3(1, TILE1), 256, SM_MMA>>>(nullptr, TILE0);

        cudaStreamWaitEvent(0, ctx.evM0, 0);
        k_gather128<<<(N_NODES * 32 + 255) / 256, 256>>>(b2, out);
    } else {
        // serial fallback
        k_deg_wsplit<<<nDegBlocks + nSplitBlocks, 256>>>(dst, E, W1, W2, nDegBlocks);
        k_scan1<<<nb, 1024>>>();
        k_scan3<<<nb, 1024>>>(E);
        k_fill<<<(E + 1023) / 1024, 256>>>(src, dst, E);
        k_scale_h<<<(M_PAD * (D0 / 4) + 255) / 256, 256>>>(x);
        k_gather256<<<(M_PAD * 32 + 255) / 256, 256>>>(0, M_PAD);
        k_mma<1><<<dim3(2, NTILE_M), 256, SM_MMA>>>(b1, 0);
        k_mma<2><<<dim3(1, NTILE_M), 256, SM_MMA>>>(nullptr, 0);
        k_gather128<<<(N_NODES * 32 + 255) / 256, 256>>>(b2, out);
    }
}